// round 16
// baseline (speedup 1.0000x reference)
#include <cuda_runtime.h>
#include <cuda_fp16.h>
#include <math.h>
#include <stdint.h>

// Problem constants
#define Bb 2
#define Ss 2048
#define Dd 1024
#define Hh 16
#define Kk 16
#define Dh 64
#define Mrows (Bb * Ss)   // 4096
#define QKVN 3072         // concatenated q|k|v row width

// ---------------- scratch (device globals; no allocation allowed) ------------
__device__ __half g_qkvh[(size_t)Mrows * QKVN]; // q|k|v concatenated fp16
__device__ float g_h[Mrows * (Dd / 2)];
__device__ int   g_topk[Bb * Kk];
__device__ unsigned char g_sel[Bb * Ss];

// fp16 buffers
__device__ __half g_a2x[(size_t)Mrows * 1024];   // x hi
__device__ __half g_aatt[(size_t)Mrows * 1024];  // att hi (written by attention)
__device__ __half g_bqkv[(size_t)QKVN * 1024];   // Wq^T|Wk^T|Wv^T hi
__device__ __half g_boh[(size_t)Dd * 1024];      // Wo^T hi
__device__ __half g_bs1h[(size_t)(Dd / 2) * 1024]; // Ws1^T hi

// ================= helpers ===================================================
__device__ __forceinline__ uint32_t smem_to_u32(const void* p) {
    uint32_t a;
    asm("{ .reg .u64 t; cvta.to.shared.u64 t, %1; cvt.u32.u64 %0, t; }" : "=r"(a) : "l"(p));
    return a;
}
__device__ __forceinline__ void cp_async16(uint32_t dst, const void* src) {
    asm volatile("cp.async.cg.shared.global [%0], [%1], 16;" :: "r"(dst), "l"(src));
}
#define CP_COMMIT() asm volatile("cp.async.commit_group;" ::: "memory")
#define CP_WAIT(n)  asm volatile("cp.async.wait_group %0;" :: "n"(n) : "memory")

__device__ __forceinline__ void ldsm_x4(uint32_t* r, uint32_t addr) {
    asm volatile("ldmatrix.sync.aligned.m8n8.x4.shared.b16 {%0,%1,%2,%3}, [%4];"
        : "=r"(r[0]), "=r"(r[1]), "=r"(r[2]), "=r"(r[3]) : "r"(addr));
}
__device__ __forceinline__ void mma16816(float* d, const uint32_t* a, const uint32_t* b) {
    asm volatile(
        "mma.sync.aligned.m16n8k16.row.col.f32.f16.f16.f32 "
        "{%0,%1,%2,%3}, {%4,%5,%6,%7}, {%8,%9}, {%0,%1,%2,%3};"
        : "+f"(d[0]), "+f"(d[1]), "+f"(d[2]), "+f"(d[3])
        : "r"(a[0]), "r"(a[1]), "r"(a[2]), "r"(a[3]), "r"(b[0]), "r"(b[1]));
}

// ================= conversion: weights (z=0..4) + x quant (z=5) ==============
__global__ __launch_bounds__(256) void convert_kernel(
    const float* __restrict__ Wq, const float* __restrict__ Wk,
    const float* __restrict__ Wv, const float* __restrict__ Wo,
    const float* __restrict__ Ws1, const float* __restrict__ x,
    __half* __restrict__ bqkv, __half* __restrict__ boh,
    __half* __restrict__ bs1h, __half* __restrict__ a2x)
{
    int z = blockIdx.z;
    int tid = threadIdx.x;
    if (z == 5) {
        // quantize x: 1024 blocks x 1024 float4s (4 float4 per thread)
        int bid = blockIdx.y * 32 + blockIdx.x;   // 0..1023
#pragma unroll
        for (int u = 0; u < 4; u++) {
            int i4 = bid * 1024 + u * 256 + tid;
            float4 a = ((const float4*)x)[i4];
            __half2* dst = (__half2*)(a2x + (size_t)i4 * 4);
            dst[0] = __floats2half2_rn(a.x, a.y);
            dst[1] = __floats2half2_rn(a.z, a.w);
        }
        return;
    }
    __shared__ float tile[32][33];
    int N = (z == 4) ? 512 : 1024;
    if (z == 4 && blockIdx.x >= 16) return;
    const float* W = (z == 0) ? Wq : (z == 1) ? Wk : (z == 2) ? Wv
                    : (z == 3) ? Wo : Ws1;
    __half* dst = (z < 3) ? (bqkv + (size_t)z * 1024 * 1024)
                : (z == 3) ? boh : bs1h;
    int tx = tid & 31, ty = tid >> 5;
    int n0 = blockIdx.x * 32, k0 = blockIdx.y * 32;
#pragma unroll
    for (int j = 0; j < 32; j += 8)
        tile[ty + j][tx] = W[(size_t)(k0 + ty + j) * N + n0 + tx];
    __syncthreads();
#pragma unroll
    for (int j = 0; j < 32; j += 8) {
        int n = ty + j;
        dst[(size_t)(n0 + n) * 1024 + k0 + tx] = __float2half(tile[tx][n]);
    }
}

// ================= persistent tensor-core GEMM (mma.sync, fp16) ==============
// Uniform config: hi x hi, K=1024 (16 iters of BK=64). Fused launch covers
// 28x32 tiles: bx<4 -> S1 (relu, fp32 Cs1 ld512), bx>=4 -> QKV (fp16 Ch).
// Plain launch (persist=0): one tile per CTA (O-proj, fp32 C).
// 3-stage cp.async pipeline, one barrier per iteration.
#define GT_SMEM_TOTAL 98304   // 3 stages x (16KB A + 16KB B)
#define GT_PERSIST_CTAS 296
#define GT_ITERS 16

__global__ __launch_bounds__(256, 2) void gemm_tc(
    const __half* __restrict__ A2, const __half* __restrict__ B2,
    const __half* __restrict__ Bs1,
    const float* __restrict__ bias0, const float* __restrict__ bias1,
    const float* __restrict__ bias2, const float* __restrict__ bias3,
    float* __restrict__ C, __half* __restrict__ Ch, float* __restrict__ Cs1,
    int ldC, int fusedS1, int halfC,
    int tilesX, int nTiles, int persist)
{
    extern __shared__ __align__(1024) char smem[];
    uint32_t sb = smem_to_u32(smem);
    int tid = threadIdx.x, lane = tid & 31, wid = tid >> 5;
    int wm = wid & 3, wn = wid >> 2;

    int r0  = tid >> 3;           // 0..31
    int c16 = tid & 7;            // 0..7
    uint32_t swoff[4];
#pragma unroll
    for (int l = 0; l < 4; l++) {
        uint32_t off = (r0 + l * 32) * 128 + c16 * 16;
        swoff[l] = off ^ ((off >> 3) & 0x70);
    }

    uint32_t a_ld[2], b_ld[4];
#pragma unroll
    for (int mt = 0; mt < 2; mt++) {
        int row = wm * 32 + mt * 16 + ((lane >> 3) & 1) * 8 + (lane & 7);
        a_ld[mt] = (uint32_t)(row * 128 + (lane >> 4) * 16);
    }
#pragma unroll
    for (int p = 0; p < 4; p++) {
        int row = wn * 64 + p * 16 + (lane >> 4) * 8 + (lane & 7);
        b_ld[p] = (uint32_t)(row * 128 + ((lane >> 3) & 1) * 16);
    }

    int stride = persist ? GT_PERSIST_CTAS : nTiles;

#pragma unroll 1
    for (int t = blockIdx.x; t < nTiles; t += stride) {
        int bx = t % tilesX;
        int by = t / tilesX;

        int isS1 = (fusedS1 && bx < 4);
        int bxl  = fusedS1 ? (isS1 ? bx : bx - 4) : bx;
        const __half* Bsel = isS1 ? Bs1 : B2;

        const __half* Abp = A2 + (size_t)by * 128 * 1024;
        const __half* Bbp = Bsel + (size_t)bxl * 128 * 1024;

        float acc[2][8][4];
#pragma unroll
        for (int mt = 0; mt < 2; mt++)
#pragma unroll
            for (int nt = 0; nt < 8; nt++)
#pragma unroll
                for (int c = 0; c < 4; c++) acc[mt][nt][c] = 0.f;

        // prologue: load iters 0,1 into stages 0,1
#pragma unroll 1
        for (int pre = 0; pre < 2; pre++) {
            int kw = pre * 64;
            const __half* Ak = Abp + kw;
            const __half* Bk = Bbp + kw;
            uint32_t abase = sb + pre * 16384;
            uint32_t bbase = sb + 49152 + pre * 16384;
#pragma unroll
            for (int l = 0; l < 4; l++) {
                int row = r0 + l * 32;
                cp_async16(abase + swoff[l], Ak + (size_t)row * 1024 + c16 * 8);
                cp_async16(bbase + swoff[l], Bk + (size_t)row * 1024 + c16 * 8);
            }
            CP_COMMIT();
        }

#pragma unroll 1
        for (int it = 0; it < GT_ITERS; ++it) {
            if (it + 1 < GT_ITERS) { CP_WAIT(1); } else { CP_WAIT(0); }
            __syncthreads();   // publishes stage it%3; protects overwrite of (it+2)%3
            if (it + 2 < GT_ITERS) {
                int kw = (it + 2) * 64;
                const __half* Ak = Abp + kw;
                const __half* Bk = Bbp + kw;
                int st = (it + 2) % 3;
                uint32_t abase = sb + st * 16384;
                uint32_t bbase = sb + 49152 + st * 16384;
#pragma unroll
                for (int l = 0; l < 4; l++) {
                    int row = r0 + l * 32;
                    cp_async16(abase + swoff[l], Ak + (size_t)row * 1024 + c16 * 8);
                    cp_async16(bbase + swoff[l], Bk + (size_t)row * 1024 + c16 * 8);
                }
                CP_COMMIT();
            }

            int st = it % 3;
            uint32_t ab  = sb + st * 16384;
            uint32_t bbS = sb + 49152 + st * 16384;
#pragma unroll
            for (int s = 0; s < 4; ++s) {
                uint32_t kb = s * 32;
                uint32_t afr[2][4];
#pragma unroll
                for (int mt = 0; mt < 2; mt++) {
                    uint32_t off = a_ld[mt] + kb;
                    ldsm_x4(afr[mt], ab + (off ^ ((off >> 3) & 0x70)));
                }
                uint32_t bfr[8][2];
#pragma unroll
                for (int p = 0; p < 4; p++) {
                    uint32_t off = b_ld[p] + kb;
                    uint32_t r[4];
                    ldsm_x4(r, bbS + (off ^ ((off >> 3) & 0x70)));
                    bfr[2 * p][0] = r[0]; bfr[2 * p][1] = r[1];
                    bfr[2 * p + 1][0] = r[2]; bfr[2 * p + 1][1] = r[3];
                }
#pragma unroll
                for (int mt = 0; mt < 2; mt++)
#pragma unroll
                    for (int nt = 0; nt < 8; nt++)
                        mma16816(acc[mt][nt], afr[mt], bfr[nt]);
            }
        }
        __syncthreads();   // last compute done before next tile's prologue writes

        // epilogue
        const float* bp;
        int bcol0;
        if (isS1) { bp = bias3; bcol0 = bxl * 128; }
        else {
            int bsel = bxl >> 3;
            bp = (bsel == 0) ? bias0 : (bsel == 1 ? bias1 : bias2);
            bcol0 = (bxl & 7) * 128;
        }

        int g = lane >> 2, t4 = lane & 3;
#pragma unroll
        for (int mt = 0; mt < 2; mt++) {
            int row = by * 128 + wm * 32 + mt * 16 + g;
#pragma unroll
            for (int nt = 0; nt < 8; nt++) {
                int coff = wn * 64 + nt * 8 + t4 * 2;
                int col = bxl * 128 + coff;
                float b0 = bp[bcol0 + coff], b1 = bp[bcol0 + coff + 1];
                float v0 = acc[mt][nt][0] + b0;
                float v1 = acc[mt][nt][1] + b1;
                float v2 = acc[mt][nt][2] + b0;
                float v3 = acc[mt][nt][3] + b1;
                if (isS1) {
                    v0 = fmaxf(v0, 0.f); v1 = fmaxf(v1, 0.f);
                    v2 = fmaxf(v2, 0.f); v3 = fmaxf(v3, 0.f);
                    *(float2*)(Cs1 + (size_t)row * 512 + col)       = make_float2(v0, v1);
                    *(float2*)(Cs1 + (size_t)(row + 8) * 512 + col) = make_float2(v2, v3);
                } else if (halfC) {
                    *(__half2*)(Ch + (size_t)row * ldC + col)       = __floats2half2_rn(v0, v1);
                    *(__half2*)(Ch + (size_t)(row + 8) * ldC + col) = __floats2half2_rn(v2, v3);
                } else {
                    *(float2*)(C + (size_t)row * ldC + col)       = make_float2(v0, v1);
                    *(float2*)(C + (size_t)(row + 8) * ldC + col) = make_float2(v2, v3);
                }
            }
        }
    }
}

// ---------------- fused importance + top-16: one block per batch -------------
// 1024 threads: each computes 2 rows' logits into smem, then warp 0 runs 16
// argmax passes. (bias/sigmoid omitted: order-preserving.)
__global__ __launch_bounds__(1024) void imptopk_kernel(
    const float* __restrict__ Hm, const float* __restrict__ Ws2,
    int* __restrict__ topk, unsigned char* __restrict__ sel)
{
    __shared__ float vals[Ss];
    int b = blockIdx.x, tid = threadIdx.x;
    const float4* w4 = (const float4*)Ws2;
#pragma unroll 1
    for (int r = 0; r < 2; r++) {
        int row = tid * 2 + r;
        const float4* hr4 = (const float4*)(Hm + (size_t)(b * Ss + row) * 512);
        float s = 0.f;
#pragma unroll 4
        for (int j = 0; j < 128; j++) {
            float4 a = hr4[j], wv = w4[j];
            s += a.x * wv.x + a.y * wv.y + a.z * wv.z + a.w * wv.w;
        }
        vals[row] = s;
        sel[b * Ss + row] = 0;
        sel[b * Ss + row + 0] = 0;
    }
    // also zero the other row handled above (tid*2 and tid*2+1 both covered)
    __syncthreads();

    if (tid < 32) {
        int lane = tid;
#pragma unroll 1
        for (int it = 0; it < Kk; it++) {
            float m = -INFINITY; int mi = 0;
            for (int j = lane; j < Ss; j += 32) {
                float v = vals[j];
                if (v > m) { m = v; mi = j; }
            }
#pragma unroll
            for (int o = 16; o > 0; o >>= 1) {
                float om = __shfl_xor_sync(0xffffffffu, m, o);
                int   oi = __shfl_xor_sync(0xffffffffu, mi, o);
                if (om > m) { m = om; mi = oi; }
            }
            mi = __shfl_sync(0xffffffffu, mi, 0);
            if (lane == 0) {
                topk[b * Kk + it] = mi;
                sel[b * Ss + mi] = 1;
            }
            vals[mi] = -INFINITY;
            __syncwarp();
        }
    }
}

// ---------------- merged attention: dense (bx<32) + sparse (bx>=32) ----------
// 512 threads. Sparse blocks: 64 queries (4 rounds of 16) per staged K/V16.
// Per-lane d-pair layout in AV loops; __half2 stores.
#define AD_QS   0                          // 16*64 floats (4KB)
#define AD_KS   4096                       // 64 x 132 floats
#define AD_VS   (4096 + 33792)             // 128 x 64 floats
#define AD_WS   (4096 + 33792 + 32768)     // 16 x 128 floats
#define AD_SMEM (4096 + 33792 + 32768 + 8192)   // 78848

__global__ __launch_bounds__(512) void attn_merged(
    const __half* __restrict__ qkv, const int* __restrict__ topk,
    const unsigned char* __restrict__ sel, __half* __restrict__ aatt)
{
    extern __shared__ __align__(16) char smraw[];
    float* qs = (float*)(smraw + AD_QS);
    float* ks = (float*)(smraw + AD_KS);
    float* vs = (float*)(smraw + AD_VS);
    float* ws = (float*)(smraw + AD_WS);

    int tid = threadIdx.x, w = tid >> 5, lane = tid & 31;

    if (blockIdx.x >= 32) {
        // ---------- sparse path: 64 queries per block, 4 rounds ----------
        int sbx = blockIdx.x - 32;           // 0..1023
        int qid0 = sbx * 64;                 // same (b,h) within the group
        int b = qid0 >> 15;
        int h = (qid0 >> 11) & 15;
        int i0 = qid0 & 2047;

        if (tid < 256) {
            int key = tid >> 4;
            int d0  = (tid & 15) * 4;
            int kj = topk[b * Kk + key];
            const __half* kr = qkv + (size_t)(b * Ss + kj) * QKVN + 1024 + h * Dh + d0;
            const __half* vr = kr + 1024;
            __half2 k0 = *(const __half2*)kr, k1 = *(const __half2*)(kr + 2);
            __half2 v0 = *(const __half2*)vr, v1 = *(const __half2*)(vr + 2);
            float2 kf0 = __half22float2(k0), kf1 = __half22float2(k1);
            float2 vf0 = __half22float2(v0), vf1 = __half22float2(v1);
            ks[key * 68 + d0 + 0] = kf0.x; ks[key * 68 + d0 + 1] = kf0.y;
            ks[key * 68 + d0 + 2] = kf1.x; ks[key * 68 + d0 + 3] = kf1.y;
            vs[key * 68 + d0 + 0] = vf0.x; vs[key * 68 + d0 + 1] = vf0.y;
            vs[key * 68 + d0 + 2] = vf1.x; vs[key * 68 + d0 + 3] = vf1.y;
        }
        __syncthreads();

#pragma unroll 1
        for (int r = 0; r < 4; r++) {
            int i = i0 + r * 16 + w;
            const __half* qr = qkv + (size_t)(b * Ss + i) * QKVN + h * Dh;
            qs[w * 64 + lane]      = __half2float(qr[lane]);
            qs[w * 64 + lane + 32] = __half2float(qr[lane + 32]);
            __syncwarp();

            if (!sel[b * Ss + i]) {
                float score = -INFINITY;
                if (lane < 16) {
                    float s = 0.f;
#pragma unroll
                    for (int d = 0; d < 64; d++) s += qs[w * 64 + d] * ks[lane * 68 + d];
                    score = s * 0.125f;
                }
                float m = score;
#pragma unroll
                for (int o = 16; o > 0; o >>= 1)
                    m = fmaxf(m, __shfl_xor_sync(0xffffffffu, m, o));
                float e = (lane < 16) ? expf(score - m) : 0.f;
                float ssum = e;
#pragma unroll
                for (int o = 16; o > 0; o >>= 1)
                    ssum += __shfl_xor_sync(0xffffffffu, ssum, o);
                float wgt = e / ssum;

                float acc0 = 0.f, acc1 = 0.f;
#pragma unroll
                for (int j = 0; j < 16; j++) {
                    float wj = __shfl_sync(0xffffffffu, wgt, j);
                    float2 v2 = *(const float2*)(vs + j * 68 + 2 * lane);
                    acc0 = fmaf(wj, v2.x, acc0);
                    acc1 = fmaf(wj, v2.y, acc1);
                }
                size_t base = (size_t)(b * Ss + i) * 1024 + h * Dh;
                *(__half2*)(aatt + base + 2 * lane) = __floats2half2_rn(acc0, acc1);
            }
            __syncwarp();
        }
        return;
    }

    // ---------- dense path: one block per (b,h), 16 warps = 16 queries -------
    int b = blockIdx.x >> 4, h = blockIdx.x & 15;
    int i = topk[b * Kk + w];

    {
        const __half* qr = qkv + (size_t)(b * Ss + i) * QKVN + h * Dh;
        qs[w * 64 + lane]      = __half2float(qr[lane]);
        qs[w * 64 + lane + 32] = __half2float(qr[lane + 32]);
    }

    float m_run = -INFINITY, sum_l = 0.f, acc0 = 0.f, acc1 = 0.f;

#pragma unroll 1
    for (int t = 0; t < 16; ++t) {
        __syncthreads();
        {
            int key = tid >> 2;
            int d0  = (tid & 3) * 16;
            const __half* kr = qkv + (size_t)(b * Ss + t * 128 + key) * QKVN + 1024 + h * Dh + d0;
            const __half* vr = kr + 1024;
#pragma unroll
            for (int u = 0; u < 4; u++) {
                __half2 kp0 = *(const __half2*)(kr + u * 4);
                __half2 kp1 = *(const __half2*)(kr + u * 4 + 2);
                float2 kf0 = __half22float2(kp0), kf1 = __half22float2(kp1);
                int d = d0 + u * 4;
                ks[(d + 0) * 132 + key] = kf0.x;
                ks[(d + 1) * 132 + key] = kf0.y;
                ks[(d + 2) * 132 + key] = kf1.x;
                ks[(d + 3) * 132 + key] = kf1.y;
                __half2 vp0 = *(const __half2*)(vr + u * 4);
                __half2 vp1 = *(const __half2*)(vr + u * 4 + 2);
                float2 vf0 = __half22float2(vp0), vf1 = __half22float2(vp1);
                *(float4*)(vs + key * 64 + d) = make_float4(vf0.x, vf0.y, vf1.x, vf1.y);
            }
        }
        __syncthreads();

        float sc4[4];
        float mloc = -INFINITY;
#pragma unroll
        for (int c = 0; c < 4; c++) {
            int kk = lane + c * 32;
            float s = 0.f;
#pragma unroll
            for (int d = 0; d < 64; d++) s += qs[w * 64 + d] * ks[d * 132 + kk];
            s *= 0.125f;
            sc4[c] = s;
            mloc = fmaxf(mloc, s);
        }
#pragma unroll
        for (int o = 16; o > 0; o >>= 1)
            mloc = fmaxf(mloc, __shfl_xor_sync(0xffffffffu, mloc, o));
        float m_new = fmaxf(m_run, mloc);
        float scale = expf(m_run - m_new);
        acc0 *= scale; acc1 *= scale; sum_l *= scale;
#pragma unroll
        for (int c = 0; c < 4; c++) {
            float wv = expf(sc4[c] - m_new);
            ws[w * 128 + lane + c * 32] = wv;
            sum_l += wv;
        }
        m_run = m_new;
        __syncwarp();
#pragma unroll 4
        for (int j = 0; j < 128; j++) {
            float wj = ws[w * 128 + j];
            float2 v2 = *(const float2*)(vs + j * 64 + 2 * lane);
            acc0 = fmaf(wj, v2.x, acc0);
            acc1 = fmaf(wj, v2.y, acc1);
        }
    }

    float sum = sum_l;
#pragma unroll
    for (int o = 16; o > 0; o >>= 1) sum += __shfl_xor_sync(0xffffffffu, sum, o);
    float inv = 1.f / sum;

    size_t base = (size_t)(b * Ss + i) * 1024 + h * Dh;
    *(__half2*)(aatt + base + 2 * lane) = __floats2half2_rn(acc0 * inv, acc1 * inv);
}

// ---------------- launcher ---------------------------------------------------
extern "C" void kernel_launch(void* const* d_in, const int* in_sizes, int n_in,
                              void* d_out, int out_size)
{
    const float* x   = (const float*)d_in[0];
    const float* Wq  = (const float*)d_in[1];
    const float* bq  = (const float*)d_in[2];
    const float* Wk  = (const float*)d_in[3];
    const float* bk  = (const float*)d_in[4];
    const float* Wv  = (const float*)d_in[5];
    const float* bv  = (const float*)d_in[6];
    const float* Wo  = (const float*)d_in[7];
    const float* bo  = (const float*)d_in[8];
    const float* Ws1 = (const float*)d_in[9];
    const float* bs1 = (const float*)d_in[10];
    const float* Ws2 = (const float*)d_in[11];
    float* out = (float*)d_out;

    float *hbuf;
    int *tkb; unsigned char *selb;
    __half *qkvh, *a2x, *aatt, *bqkv, *boh, *bs1h;
    cudaGetSymbolAddress((void**)&qkvh, g_qkvh);
    cudaGetSymbolAddress((void**)&hbuf, g_h);
    cudaGetSymbolAddress((void**)&tkb,  g_topk);
    cudaGetSymbolAddress((void**)&selb, g_sel);
    cudaGetSymbolAddress((void**)&a2x,  g_a2x);
    cudaGetSymbolAddress((void**)&aatt, g_aatt);
    cudaGetSymbolAddress((void**)&bqkv, g_bqkv);
    cudaGetSymbolAddress((void**)&boh,  g_boh);
    cudaGetSymbolAddress((void**)&bs1h, g_bs1h);

    cudaFuncSetAttribute(gemm_tc, cudaFuncAttributeMaxDynamicSharedMemorySize,
                         GT_SMEM_TOTAL);
    cudaFuncSetAttribute(attn_merged, cudaFuncAttributeMaxDynamicSharedMemorySize,
                         AD_SMEM);

    // conversions: weights (z=0..4) + x quant (z=5) in one launch
    convert_kernel<<<dim3(32, 32, 6), 256>>>(Wq, Wk, Wv, Wo, Ws1, x,
                                             bqkv, boh, bs1h, a2x);

    // persistent fused S1 (bx<4, relu -> fp32 hbuf) + QKV (bx>=4 -> fp16 qkv)
    gemm_tc<<<GT_PERSIST_CTAS, 256, GT_SMEM_TOTAL>>>(
        a2x, bqkv, bs1h, bq, bk, bv, bs1, nullptr, qkvh, hbuf,
        QKVN, 1, 1,
        QKVN / 128 + 4, (QKVN / 128 + 4) * (Mrows / 128), 1);

    // fused importance + top-k, then merged attention
    imptopk_kernel<<<Bb, 1024>>>(hbuf, Ws2, tkb, selb);
    attn_merged<<<32 + (Bb * Hh * Ss) / 64, 512, AD_SMEM>>>(qkvh, tkb, selb, aatt);

    // output projection (hi x hi -> fp32 out): 8x32 = 256 tiles, one wave
    gemm_tc<<<256, 256, GT_SMEM_TOTAL>>>(
        aatt, boh, nullptr, bo, bo, bo, nullptr, out, nullptr, nullptr,
        Dd, 0, 0,
        Dd / 128, 256, 0);
}

// round 17
// speedup vs baseline: 1.8900x; 1.8900x over previous
#include <cuda_runtime.h>
#include <cuda_fp16.h>
#include <math.h>
#include <stdint.h>

// Problem constants
#define Bb 2
#define Ss 2048
#define Dd 1024
#define Hh 16
#define Kk 16
#define Dh 64
#define Mrows (Bb * Ss)   // 4096
#define QKVN 3072         // concatenated q|k|v row width

// ---------------- scratch (device globals; no allocation allowed) ------------
__device__ __half g_qkvh[(size_t)Mrows * QKVN]; // q|k|v concatenated fp16
__device__ float g_h[Mrows * (Dd / 2)];
__device__ float g_imp[Mrows];
__device__ int   g_topk[Bb * Kk];
__device__ unsigned char g_sel[Bb * Ss];

// dense split-KV partials: (b,h,chunk,iq)
__device__ float g_pm[Bb * Hh * 4 * 16];
__device__ float g_psum[Bb * Hh * 4 * 16];
__device__ float g_pacc[Bb * Hh * 4 * 16 * 64];

// fp16 buffers
__device__ __half g_a2x[(size_t)Mrows * 1024];   // x hi
__device__ __half g_aatt[(size_t)Mrows * 1024];  // att hi (written by attention)
__device__ __half g_bqkv[(size_t)QKVN * 1024];   // Wq^T|Wk^T|Wv^T hi
__device__ __half g_boh[(size_t)Dd * 1024];      // Wo^T hi
__device__ __half g_bs1h[(size_t)(Dd / 2) * 1024]; // Ws1^T hi

// ================= helpers ===================================================
__device__ __forceinline__ uint32_t smem_to_u32(const void* p) {
    uint32_t a;
    asm("{ .reg .u64 t; cvta.to.shared.u64 t, %1; cvt.u32.u64 %0, t; }" : "=r"(a) : "l"(p));
    return a;
}
__device__ __forceinline__ void cp_async16(uint32_t dst, const void* src) {
    asm volatile("cp.async.cg.shared.global [%0], [%1], 16;" :: "r"(dst), "l"(src));
}
#define CP_COMMIT() asm volatile("cp.async.commit_group;" ::: "memory")
#define CP_WAIT(n)  asm volatile("cp.async.wait_group %0;" :: "n"(n) : "memory")

__device__ __forceinline__ void ldsm_x4(uint32_t* r, uint32_t addr) {
    asm volatile("ldmatrix.sync.aligned.m8n8.x4.shared.b16 {%0,%1,%2,%3}, [%4];"
        : "=r"(r[0]), "=r"(r[1]), "=r"(r[2]), "=r"(r[3]) : "r"(addr));
}
__device__ __forceinline__ void mma16816(float* d, const uint32_t* a, const uint32_t* b) {
    asm volatile(
        "mma.sync.aligned.m16n8k16.row.col.f32.f16.f16.f32 "
        "{%0,%1,%2,%3}, {%4,%5,%6,%7}, {%8,%9}, {%0,%1,%2,%3};"
        : "+f"(d[0]), "+f"(d[1]), "+f"(d[2]), "+f"(d[3])
        : "r"(a[0]), "r"(a[1]), "r"(a[2]), "r"(a[3]), "r"(b[0]), "r"(b[1]));
}

// ================= conversion kernels ========================================
// fp32 [M,1024] -> fp16 hi [M,1024], contiguous float4 -> half2 x2
__global__ __launch_bounds__(256) void quantA_kernel(
    const float* __restrict__ A, __half* __restrict__ Ah)
{
    int i4 = blockIdx.x * 256 + threadIdx.x;
    float4 a = ((const float4*)A)[i4];
    __half2* dst = (__half2*)(Ah + (size_t)i4 * 4);
    dst[0] = __floats2half2_rn(a.x, a.y);
    dst[1] = __floats2half2_rn(a.z, a.w);
}

// Batched weight transpose+quantize. z=0,1,2 -> bqkv; z=3 -> boh; z=4 -> bs1h.
__global__ __launch_bounds__(256) void splitWh5_kernel(
    const float* __restrict__ Wq, const float* __restrict__ Wk,
    const float* __restrict__ Wv, const float* __restrict__ Wo,
    const float* __restrict__ Ws1,
    __half* __restrict__ bqkv, __half* __restrict__ boh,
    __half* __restrict__ bs1h)
{
    __shared__ float tile[32][33];
    int z = blockIdx.z;
    int N = (z == 4) ? 512 : 1024;
    if (z == 4 && blockIdx.x >= 16) return;
    const float* W = (z == 0) ? Wq : (z == 1) ? Wk : (z == 2) ? Wv
                    : (z == 3) ? Wo : Ws1;
    __half* dst = (z < 3) ? (bqkv + (size_t)z * 1024 * 1024)
                : (z == 3) ? boh : bs1h;
    int tx = threadIdx.x & 31, ty = threadIdx.x >> 5;
    int n0 = blockIdx.x * 32, k0 = blockIdx.y * 32;
#pragma unroll
    for (int j = 0; j < 32; j += 8)
        tile[ty + j][tx] = W[(size_t)(k0 + ty + j) * N + n0 + tx];
    __syncthreads();
#pragma unroll
    for (int j = 0; j < 32; j += 8) {
        int n = ty + j;
        dst[(size_t)(n0 + n) * 1024 + k0 + tx] = __float2half(tile[tx][n]);
    }
}

// ================= persistent tensor-core GEMM (mma.sync, fp16) ==============
#define GT_SMEM_TOTAL 98304   // 3 stages x (16KB A + 16KB B)
#define GT_PERSIST_CTAS 296
#define GT_ITERS 16

__global__ __launch_bounds__(256, 2) void gemm_tc(
    const __half* __restrict__ A2, const __half* __restrict__ B2,
    const __half* __restrict__ Bs1,
    const float* __restrict__ bias0, const float* __restrict__ bias1,
    const float* __restrict__ bias2, const float* __restrict__ bias3,
    float* __restrict__ C, __half* __restrict__ Ch, float* __restrict__ Cs1,
    int ldC, int fusedS1, int halfC,
    int tilesX, int nTiles, int persist)
{
    extern __shared__ __align__(1024) char smem[];
    uint32_t sb = smem_to_u32(smem);
    int tid = threadIdx.x, lane = tid & 31, wid = tid >> 5;
    int wm = wid & 3, wn = wid >> 2;

    int r0  = tid >> 3;           // 0..31
    int c16 = tid & 7;            // 0..7
    uint32_t swoff[4];
#pragma unroll
    for (int l = 0; l < 4; l++) {
        uint32_t off = (r0 + l * 32) * 128 + c16 * 16;
        swoff[l] = off ^ ((off >> 3) & 0x70);
    }

    uint32_t a_ld[2], b_ld[4];
#pragma unroll
    for (int mt = 0; mt < 2; mt++) {
        int row = wm * 32 + mt * 16 + ((lane >> 3) & 1) * 8 + (lane & 7);
        a_ld[mt] = (uint32_t)(row * 128 + (lane >> 4) * 16);
    }
#pragma unroll
    for (int p = 0; p < 4; p++) {
        int row = wn * 64 + p * 16 + (lane >> 4) * 8 + (lane & 7);
        b_ld[p] = (uint32_t)(row * 128 + ((lane >> 3) & 1) * 16);
    }

    int stride = persist ? GT_PERSIST_CTAS : nTiles;

#pragma unroll 1
    for (int t = blockIdx.x; t < nTiles; t += stride) {
        int bx = t % tilesX;
        int by = t / tilesX;

        int isS1 = (fusedS1 && bx < 4);
        int bxl  = fusedS1 ? (isS1 ? bx : bx - 4) : bx;
        const __half* Bsel = isS1 ? Bs1 : B2;

        const __half* Abp = A2 + (size_t)by * 128 * 1024;
        const __half* Bbp = Bsel + (size_t)bxl * 128 * 1024;

        float acc[2][8][4];
#pragma unroll
        for (int mt = 0; mt < 2; mt++)
#pragma unroll
            for (int nt = 0; nt < 8; nt++)
#pragma unroll
                for (int c = 0; c < 4; c++) acc[mt][nt][c] = 0.f;

        // prologue: load iters 0,1 into stages 0,1
#pragma unroll 1
        for (int pre = 0; pre < 2; pre++) {
            int kw = pre * 64;
            const __half* Ak = Abp + kw;
            const __half* Bk = Bbp + kw;
            uint32_t abase = sb + pre * 16384;
            uint32_t bbase = sb + 49152 + pre * 16384;
#pragma unroll
            for (int l = 0; l < 4; l++) {
                int row = r0 + l * 32;
                cp_async16(abase + swoff[l], Ak + (size_t)row * 1024 + c16 * 8);
                cp_async16(bbase + swoff[l], Bk + (size_t)row * 1024 + c16 * 8);
            }
            CP_COMMIT();
        }

#pragma unroll 1
        for (int it = 0; it < GT_ITERS; ++it) {
            if (it + 1 < GT_ITERS) { CP_WAIT(1); } else { CP_WAIT(0); }
            __syncthreads();   // publishes stage it%3; protects overwrite of (it+2)%3
            if (it + 2 < GT_ITERS) {
                int kw = (it + 2) * 64;
                const __half* Ak = Abp + kw;
                const __half* Bk = Bbp + kw;
                int st = (it + 2) % 3;
                uint32_t abase = sb + st * 16384;
                uint32_t bbase = sb + 49152 + st * 16384;
#pragma unroll
                for (int l = 0; l < 4; l++) {
                    int row = r0 + l * 32;
                    cp_async16(abase + swoff[l], Ak + (size_t)row * 1024 + c16 * 8);
                    cp_async16(bbase + swoff[l], Bk + (size_t)row * 1024 + c16 * 8);
                }
                CP_COMMIT();
            }

            int st = it % 3;
            uint32_t ab  = sb + st * 16384;
            uint32_t bbS = sb + 49152 + st * 16384;
#pragma unroll
            for (int s = 0; s < 4; ++s) {
                uint32_t kb = s * 32;
                uint32_t afr[2][4];
#pragma unroll
                for (int mt = 0; mt < 2; mt++) {
                    uint32_t off = a_ld[mt] + kb;
                    ldsm_x4(afr[mt], ab + (off ^ ((off >> 3) & 0x70)));
                }
                uint32_t bfr[8][2];
#pragma unroll
                for (int p = 0; p < 4; p++) {
                    uint32_t off = b_ld[p] + kb;
                    uint32_t r[4];
                    ldsm_x4(r, bbS + (off ^ ((off >> 3) & 0x70)));
                    bfr[2 * p][0] = r[0]; bfr[2 * p][1] = r[1];
                    bfr[2 * p + 1][0] = r[2]; bfr[2 * p + 1][1] = r[3];
                }
#pragma unroll
                for (int mt = 0; mt < 2; mt++)
#pragma unroll
                    for (int nt = 0; nt < 8; nt++)
                        mma16816(acc[mt][nt], afr[mt], bfr[nt]);
            }
        }
        __syncthreads();   // last compute done before next tile's prologue writes

        // epilogue
        const float* bp;
        int bcol0;
        if (isS1) { bp = bias3; bcol0 = bxl * 128; }
        else {
            int bsel = bxl >> 3;
            bp = (bsel == 0) ? bias0 : (bsel == 1 ? bias1 : bias2);
            bcol0 = (bxl & 7) * 128;
        }

        int g = lane >> 2, t4 = lane & 3;
#pragma unroll
        for (int mt = 0; mt < 2; mt++) {
            int row = by * 128 + wm * 32 + mt * 16 + g;
#pragma unroll
            for (int nt = 0; nt < 8; nt++) {
                int coff = wn * 64 + nt * 8 + t4 * 2;
                int col = bxl * 128 + coff;
                float b0 = bp[bcol0 + coff], b1 = bp[bcol0 + coff + 1];
                float v0 = acc[mt][nt][0] + b0;
                float v1 = acc[mt][nt][1] + b1;
                float v2 = acc[mt][nt][2] + b0;
                float v3 = acc[mt][nt][3] + b1;
                if (isS1) {
                    v0 = fmaxf(v0, 0.f); v1 = fmaxf(v1, 0.f);
                    v2 = fmaxf(v2, 0.f); v3 = fmaxf(v3, 0.f);
                    *(float2*)(Cs1 + (size_t)row * 512 + col)       = make_float2(v0, v1);
                    *(float2*)(Cs1 + (size_t)(row + 8) * 512 + col) = make_float2(v2, v3);
                } else if (halfC) {
                    *(__half2*)(Ch + (size_t)row * ldC + col)       = __floats2half2_rn(v0, v1);
                    *(__half2*)(Ch + (size_t)(row + 8) * ldC + col) = __floats2half2_rn(v2, v3);
                } else {
                    *(float2*)(C + (size_t)row * ldC + col)       = make_float2(v0, v1);
                    *(float2*)(C + (size_t)(row + 8) * ldC + col) = make_float2(v2, v3);
                }
            }
        }
    }
}

// ---------------- importance logits (float4 loads) ---------------------------
__global__ __launch_bounds__(256) void imp_kernel(
    const float* __restrict__ Hm, const float* __restrict__ Ws2,
    float* __restrict__ imp)
{
    int row  = blockIdx.x * 8 + (threadIdx.x >> 5);
    int lane = threadIdx.x & 31;
    const float4* hr4 = (const float4*)(Hm + (size_t)row * 512);
    const float4* w4  = (const float4*)Ws2;
    float s = 0.f;
#pragma unroll
    for (int j = lane; j < 128; j += 32) {
        float4 a = hr4[j], b = w4[j];
        s += a.x * b.x + a.y * b.y + a.z * b.z + a.w * b.w;
    }
#pragma unroll
    for (int o = 16; o > 0; o >>= 1) s += __shfl_xor_sync(0xffffffffu, s, o);
    if (lane == 0) imp[row] = s;
}

// ---------------- per-batch top-16: one warp per batch -----------------------
__global__ __launch_bounds__(32) void topk_kernel(
    const float* __restrict__ imp, int* __restrict__ topk,
    unsigned char* __restrict__ sel)
{
    __shared__ float vals[Ss];
    int b = blockIdx.x, lane = threadIdx.x;
    for (int j = lane; j < Ss; j += 32) {
        vals[j] = imp[b * Ss + j];
        sel[b * Ss + j] = 0;
    }
    __syncwarp();
    for (int it = 0; it < Kk; it++) {
        float m = -INFINITY; int mi = 0;
        for (int j = lane; j < Ss; j += 32) {
            float v = vals[j];
            if (v > m) { m = v; mi = j; }
        }
#pragma unroll
        for (int o = 16; o > 0; o >>= 1) {
            float om = __shfl_xor_sync(0xffffffffu, m, o);
            int   oi = __shfl_xor_sync(0xffffffffu, mi, o);
            if (om > m) { m = om; mi = oi; }
        }
        mi = __shfl_sync(0xffffffffu, mi, 0);
        if (lane == 0) {
            topk[b * Kk + it] = mi;
            sel[b * Ss + mi] = 1;
        }
        vals[mi] = -INFINITY;
        __syncwarp();
    }
}

// ---------------- merged attention: dense split-KV (bx<128) + sparse ---------
// Dense: 128 blocks = (b,h,chunk); each walks 4 K-tiles of 128 keys and writes
// flash partials (m, sum, acc[64]) per query. Sparse: 32 q/block, 2 rounds.
#define AD_QS   0                          // 16*64 floats (4KB)
#define AD_KS   4096                       // 64 x 132 floats
#define AD_VS   (4096 + 33792)             // 128 x 64 floats
#define AD_WS   (4096 + 33792 + 32768)     // 16 x 128 floats
#define AD_SMEM (4096 + 33792 + 32768 + 8192)   // 78848

__global__ __launch_bounds__(512) void attn_merged(
    const __half* __restrict__ qkv, const int* __restrict__ topk,
    const unsigned char* __restrict__ sel, __half* __restrict__ aatt,
    float* __restrict__ pm, float* __restrict__ psum, float* __restrict__ pacc)
{
    extern __shared__ __align__(16) char smraw[];
    float* qs = (float*)(smraw + AD_QS);
    float* ks = (float*)(smraw + AD_KS);
    float* vs = (float*)(smraw + AD_VS);
    float* ws = (float*)(smraw + AD_WS);

    int tid = threadIdx.x, w = tid >> 5, lane = tid & 31;

    if (blockIdx.x >= 128) {
        // ---------- sparse path: 32 queries per block, 2 rounds ----------
        int sbx = blockIdx.x - 128;          // 0..2047
        int qid0 = sbx * 32;                 // same (b,h) within the group
        int b = qid0 >> 15;
        int h = (qid0 >> 11) & 15;
        int i0 = qid0 & 2047;

        if (tid < 256) {
            int key = tid >> 4;
            int d0  = (tid & 15) * 4;
            int kj = topk[b * Kk + key];
            const __half* kr = qkv + (size_t)(b * Ss + kj) * QKVN + 1024 + h * Dh + d0;
            const __half* vr = kr + 1024;
            __half2 k0 = *(const __half2*)kr, k1 = *(const __half2*)(kr + 2);
            __half2 v0 = *(const __half2*)vr, v1 = *(const __half2*)(vr + 2);
            float2 kf0 = __half22float2(k0), kf1 = __half22float2(k1);
            float2 vf0 = __half22float2(v0), vf1 = __half22float2(v1);
            ks[key * 68 + d0 + 0] = kf0.x; ks[key * 68 + d0 + 1] = kf0.y;
            ks[key * 68 + d0 + 2] = kf1.x; ks[key * 68 + d0 + 3] = kf1.y;
            vs[key * 68 + d0 + 0] = vf0.x; vs[key * 68 + d0 + 1] = vf0.y;
            vs[key * 68 + d0 + 2] = vf1.x; vs[key * 68 + d0 + 3] = vf1.y;
        }
        __syncthreads();

#pragma unroll 1
        for (int r = 0; r < 2; r++) {
            int i = i0 + r * 16 + w;
            const __half* qr = qkv + (size_t)(b * Ss + i) * QKVN + h * Dh;
            qs[w * 64 + lane]      = __half2float(qr[lane]);
            qs[w * 64 + lane + 32] = __half2float(qr[lane + 32]);
            __syncwarp();

            if (!sel[b * Ss + i]) {
                float score = -INFINITY;
                if (lane < 16) {
                    float s = 0.f;
#pragma unroll
                    for (int d = 0; d < 64; d++) s += qs[w * 64 + d] * ks[lane * 68 + d];
                    score = s * 0.125f;
                }
                float m = score;
#pragma unroll
                for (int o = 16; o > 0; o >>= 1)
                    m = fmaxf(m, __shfl_xor_sync(0xffffffffu, m, o));
                float e = (lane < 16) ? expf(score - m) : 0.f;
                float ssum = e;
#pragma unroll
                for (int o = 16; o > 0; o >>= 1)
                    ssum += __shfl_xor_sync(0xffffffffu, ssum, o);
                float wgt = e / ssum;

                float acc0 = 0.f, acc1 = 0.f;
#pragma unroll
                for (int j = 0; j < 16; j++) {
                    float wj = __shfl_sync(0xffffffffu, wgt, j);
                    float2 v2 = *(const float2*)(vs + j * 68 + 2 * lane);
                    acc0 = fmaf(wj, v2.x, acc0);
                    acc1 = fmaf(wj, v2.y, acc1);
                }
                size_t base = (size_t)(b * Ss + i) * 1024 + h * Dh;
                *(__half2*)(aatt + base + 2 * lane) = __floats2half2_rn(acc0, acc1);
            }
            __syncwarp();
        }
        return;
    }

    // ---------- dense path: block = (b, h, chunk); 4 K-tiles of 128 ----------
    int idx = blockIdx.x;                 // 0..127
    int b = idx >> 6;
    int rem = idx & 63;
    int h = rem >> 2;
    int chunk = rem & 3;
    int i = topk[b * Kk + w];

    {
        const __half* qr = qkv + (size_t)(b * Ss + i) * QKVN + h * Dh;
        qs[w * 64 + lane]      = __half2float(qr[lane]);
        qs[w * 64 + lane + 32] = __half2float(qr[lane + 32]);
    }

    float m_run = -INFINITY, sum_l = 0.f, acc0 = 0.f, acc1 = 0.f;

#pragma unroll 1
    for (int tt = 0; tt < 4; ++tt) {
        int t = chunk * 4 + tt;
        __syncthreads();
        {
            int key = tid >> 2;
            int d0  = (tid & 3) * 16;
            const __half* kr = qkv + (size_t)(b * Ss + t * 128 + key) * QKVN + 1024 + h * Dh + d0;
            const __half* vr = kr + 1024;
#pragma unroll
            for (int u = 0; u < 4; u++) {
                __half2 kp0 = *(const __half2*)(kr + u * 4);
                __half2 kp1 = *(const __half2*)(kr + u * 4 + 2);
                float2 kf0 = __half22float2(kp0), kf1 = __half22float2(kp1);
                int d = d0 + u * 4;
                ks[(d + 0) * 132 + key] = kf0.x;
                ks[(d + 1) * 132 + key] = kf0.y;
                ks[(d + 2) * 132 + key] = kf1.x;
                ks[(d + 3) * 132 + key] = kf1.y;
                __half2 vp0 = *(const __half2*)(vr + u * 4);
                __half2 vp1 = *(const __half2*)(vr + u * 4 + 2);
                float2 vf0 = __half22float2(vp0), vf1 = __half22float2(vp1);
                *(float4*)(vs + key * 64 + d) = make_float4(vf0.x, vf0.y, vf1.x, vf1.y);
            }
        }
        __syncthreads();

        float sc4[4];
        float mloc = -INFINITY;
#pragma unroll
        for (int c = 0; c < 4; c++) {
            int kk = lane + c * 32;
            float s = 0.f;
#pragma unroll
            for (int d = 0; d < 64; d++) s += qs[w * 64 + d] * ks[d * 132 + kk];
            s *= 0.125f;
            sc4[c] = s;
            mloc = fmaxf(mloc, s);
        }
#pragma unroll
        for (int o = 16; o > 0; o >>= 1)
            mloc = fmaxf(mloc, __shfl_xor_sync(0xffffffffu, mloc, o));
        float m_new = fmaxf(m_run, mloc);
        float scale = expf(m_run - m_new);
        acc0 *= scale; acc1 *= scale; sum_l *= scale;
#pragma unroll
        for (int c = 0; c < 4; c++) {
            float wv = expf(sc4[c] - m_new);
            ws[w * 128 + lane + c * 32] = wv;
            sum_l += wv;
        }
        m_run = m_new;
        __syncwarp();
#pragma unroll 4
        for (int j = 0; j < 128; j++) {
            float wj = ws[w * 128 + j];
            float2 v2 = *(const float2*)(vs + j * 64 + 2 * lane);
            acc0 = fmaf(wj, v2.x, acc0);
            acc1 = fmaf(wj, v2.y, acc1);
        }
    }

    float sum = sum_l;
#pragma unroll
    for (int o = 16; o > 0; o >>= 1) sum += __shfl_xor_sync(0xffffffffu, sum, o);

    // write partials: slot = ((b*Hh + h)*4 + chunk)*16 + w
    int slot = ((b * Hh + h) * 4 + chunk) * 16 + w;
    if (lane == 0) { pm[slot] = m_run; psum[slot] = sum; }
    *(float2*)(pacc + (size_t)slot * 64 + 2 * lane) = make_float2(acc0, acc1);
}

// ---------------- dense split-KV reduction: 32 blocks = (b,h) ----------------
__global__ __launch_bounds__(512) void dense_reduce(
    const int* __restrict__ topk, const float* __restrict__ pm,
    const float* __restrict__ psum, const float* __restrict__ pacc,
    __half* __restrict__ aatt)
{
    int bh = blockIdx.x;            // 0..31
    int b = bh >> 4, h = bh & 15;
    int w = threadIdx.x >> 5, lane = threadIdx.x & 31;
    int i = topk[b * Kk + w];

    int base = (bh * 4) * 16 + w;   // chunk stride = 16
    float m0 = pm[base], m1 = pm[base + 16], m2 = pm[base + 32], m3 = pm[base + 48];
    float M = fmaxf(fmaxf(m0, m1), fmaxf(m2, m3));
    float w0 = expf(m0 - M), w1 = expf(m1 - M), w2 = expf(m2 - M), w3 = expf(m3 - M);
    float tot = psum[base] * w0 + psum[base + 16] * w1
              + psum[base + 32] * w2 + psum[base + 48] * w3;
    float inv = 1.f / tot;

    float2 a0 = *(const float2*)(pacc + (size_t)(base)      * 64 + 2 * lane);
    float2 a1 = *(const float2*)(pacc + (size_t)(base + 16) * 64 + 2 * lane);
    float2 a2 = *(const float2*)(pacc + (size_t)(base + 32) * 64 + 2 * lane);
    float2 a3 = *(const float2*)(pacc + (size_t)(base + 48) * 64 + 2 * lane);
    float o0 = (a0.x * w0 + a1.x * w1 + a2.x * w2 + a3.x * w3) * inv;
    float o1 = (a0.y * w0 + a1.y * w1 + a2.y * w2 + a3.y * w3) * inv;

    size_t obase = (size_t)(b * Ss + i) * 1024 + h * Dh;
    *(__half2*)(aatt + obase + 2 * lane) = __floats2half2_rn(o0, o1);
}

// ---------------- launcher ---------------------------------------------------
extern "C" void kernel_launch(void* const* d_in, const int* in_sizes, int n_in,
                              void* d_out, int out_size)
{
    const float* x   = (const float*)d_in[0];
    const float* Wq  = (const float*)d_in[1];
    const float* bq  = (const float*)d_in[2];
    const float* Wk  = (const float*)d_in[3];
    const float* bk  = (const float*)d_in[4];
    const float* Wv  = (const float*)d_in[5];
    const float* bv  = (const float*)d_in[6];
    const float* Wo  = (const float*)d_in[7];
    const float* bo  = (const float*)d_in[8];
    const float* Ws1 = (const float*)d_in[9];
    const float* bs1 = (const float*)d_in[10];
    const float* Ws2 = (const float*)d_in[11];
    float* out = (float*)d_out;

    float *hbuf, *impb, *pmb, *psb, *pab;
    int *tkb; unsigned char *selb;
    __half *qkvh, *a2x, *aatt, *bqkv, *boh, *bs1h;
    cudaGetSymbolAddress((void**)&qkvh, g_qkvh);
    cudaGetSymbolAddress((void**)&hbuf, g_h);
    cudaGetSymbolAddress((void**)&impb, g_imp);
    cudaGetSymbolAddress((void**)&tkb,  g_topk);
    cudaGetSymbolAddress((void**)&selb, g_sel);
    cudaGetSymbolAddress((void**)&a2x,  g_a2x);
    cudaGetSymbolAddress((void**)&aatt, g_aatt);
    cudaGetSymbolAddress((void**)&bqkv, g_bqkv);
    cudaGetSymbolAddress((void**)&boh,  g_boh);
    cudaGetSymbolAddress((void**)&bs1h, g_bs1h);
    cudaGetSymbolAddress((void**)&pmb,  g_pm);
    cudaGetSymbolAddress((void**)&psb,  g_psum);
    cudaGetSymbolAddress((void**)&pab,  g_pacc);

    cudaFuncSetAttribute(gemm_tc, cudaFuncAttributeMaxDynamicSharedMemorySize,
                         GT_SMEM_TOTAL);
    cudaFuncSetAttribute(attn_merged, cudaFuncAttributeMaxDynamicSharedMemorySize,
                         AD_SMEM);

    // conversions
    quantA_kernel<<<(Mrows * Dd) / 1024, 256>>>(x, a2x);
    splitWh5_kernel<<<dim3(32, 32, 5), 256>>>(Wq, Wk, Wv, Wo, Ws1, bqkv, boh, bs1h);

    // persistent fused S1 (bx<4, relu -> fp32 hbuf) + QKV (bx>=4 -> fp16 qkv)
    gemm_tc<<<GT_PERSIST_CTAS, 256, GT_SMEM_TOTAL>>>(
        a2x, bqkv, bs1h, bq, bk, bv, bs1, nullptr, qkvh, hbuf,
        QKVN, 1, 1,
        QKVN / 128 + 4, (QKVN / 128 + 4) * (Mrows / 128), 1);

    // indexer + top-k + attention (dense split-KV + sparse) + dense reduce
    imp_kernel<<<Mrows / 8, 256>>>(hbuf, Ws2, impb);
    topk_kernel<<<Bb, 32>>>(impb, tkb, selb);
    attn_merged<<<128 + (Bb * Hh * Ss) / 32, 512, AD_SMEM>>>(
        qkvh, tkb, selb, aatt, pmb, psb, pab);
    dense_reduce<<<Bb * Hh, 512>>>(tkb, pmb, psb, pab, aatt);

    // output projection (hi x hi -> fp32 out): 8x32 = 256 tiles, one wave
    gemm_tc<<<256, 256, GT_SMEM_TOTAL>>>(
        aatt, boh, nullptr, bo, bo, bo, nullptr, out, nullptr, nullptr,
        Dd, 0, 0,
        Dd / 128, 256, 0);
}